// round 15
// baseline (speedup 1.0000x reference)
#include <cuda_runtime.h>
#include <cstdint>

// ComplexUpSampling2D (resolved interface):
//   inputs : x_re, x_im fp32 [16,128,128,64] (64 MiB each; x_im unused)
//   output : float32 [16,256,256,64] = 67,108,864 elems (268 MiB)
//            = real part of nearest 2x2 complex upsample
//   out[b,oi,oj,c] = x_re[b, oi/2, oj/2, c]
//
// R15: OUTPUT-centric mapping. One thread = one output float4; the grid
// writes the output buffer in strictly ascending address order (perfect
// 512B-per-warp contiguous store runs -> optimal L2->DRAM write drain).
// Reads are 4x amplified but L2-resident by construction: within a warp,
// lanes 0-15 and 16-31 request the same 256B input chunk (oj and oj+1
// share the same input pixel), and row pairs 2h/2h+1 map to adjacent
// blocks. __stcs on stores (evict-first) keeps L2 capacity for the input;
// __ldg on loads uses the read-only path.

static constexpr long long NEXP    = 16LL * 128 * 128 * 64;   // input floats  = 16,777,216
static constexpr long long OUT_F   = 4 * NEXP;                // output floats = 67,108,864
static constexpr unsigned  OUT_F4N = (unsigned)(OUT_F / 4);   // output float4 = 16,777,216

__global__ void __launch_bounds__(256)
up2x_real_out_f4(const float4* __restrict__ re, float4* __restrict__ out,
                 unsigned n_out_f4)
{
    unsigned tid = blockIdx.x * blockDim.x + threadIdx.x;
    if (tid >= n_out_f4) return;

    // Output f4 layout: tid = ((b*256 + oi)*256 + oj)*16 + c4
    unsigned c4   = tid & 15u;          // float4 group within C=64
    unsigned oj   = (tid >> 4) & 255u;  // output column
    unsigned rowg = tid >> 12;          // b*256 + oi   (0..4095)

    // Input f4 index: ((b*128 + oi/2)*128 + oj/2)*16 + c4
    //   b*128 + oi/2 == rowg >> 1  (256 even)
    unsigned in_idx = (((rowg >> 1) << 7) + (oj >> 1)) * 16u + c4;

    float4 v = __ldg(re + in_idx);
    __stcs(out + tid, v);
}

// Scalar fallback (alignment), same mapping.
__global__ void __launch_bounds__(256)
up2x_real_out_scalar(const float* __restrict__ re, float* __restrict__ out,
                     long long n_out)
{
    long long e = blockIdx.x * (long long)blockDim.x + threadIdx.x;
    if (e >= n_out) return;

    unsigned c    = (unsigned)(e & 63);
    unsigned oj   = (unsigned)((e >> 6) & 255);
    unsigned rowg = (unsigned)(e >> 14);

    long long in_idx = (((long long)(rowg >> 1) << 7) + (oj >> 1)) * 64 + c;
    out[e] = __ldg(re + in_idx);
}

extern "C" void kernel_launch(void* const* d_in, const int* in_sizes, int n_in,
                              void* d_out, int out_size)
{
    // Locate x_re by size (element- or byte-count), not position.
    int ire = -1;
    for (int i = 0; i < n_in; i++) {
        long long s = in_sizes[i];
        if (s == NEXP || s == NEXP * 4) { ire = i; break; }
    }
    if (ire < 0) ire = 0;

    const float* re_p = (const float*)d_in[ire];
    float* out_p = (float*)d_out;

    // Output extent: min(out_size, OUT_F) floats — safe under element- or
    // byte-count readings of out_size (byte reading => buffer 4x bigger).
    long long n_out = (long long)out_size;
    if (n_out < 0) n_out = 0;
    if (n_out > OUT_F) n_out = OUT_F;

    bool aligned =
        ((((uintptr_t)re_p) | ((uintptr_t)out_p)) & 15) == 0 && (n_out % 4 == 0);

    const int block = 256;

    if (aligned) {
        unsigned n_out_f4 = (unsigned)(n_out / 4);              // 16,777,216
        int grid = (int)((n_out_f4 + block - 1) / block);       // 65,536
        if (grid > 0)
            up2x_real_out_f4<<<grid, block>>>((const float4*)re_p,
                                              (float4*)out_p, n_out_f4);
    } else {
        long long grid_ll = (n_out + block - 1) / block;
        if (grid_ll > 0)
            up2x_real_out_scalar<<<(int)grid_ll, block>>>(re_p, out_p, n_out);
    }
}